// round 5
// baseline (speedup 1.0000x reference)
#include <cuda_runtime.h>

#define NN 50000
#define NE 800000
#define L 128
#define KEFF 24   // 16 node feats + 3 agg_s + 1 cnt_s + 3 agg_r + 1 cnt_r
#define NPAIR (NN / 2)          // 25000
#define NUNIT (NPAIR * 4)       // 100000  (pair x j-quarter)

// Scratch (__device__ globals; no allocation allowed)
__device__ float g_agg[NN * 8];       // per node: {s0,s1,s2,cnt_s, r0,r1,r2,cnt_r}
__device__ float g_W1eff[L * KEFF];   // [j*24+k] folded layer-1 weight
__device__ float g_b1eff[L];          // folded layer-1 bias
__device__ float g_w2d[L];            // W2 @ W_dn
__device__ float g_cd[1];             // b2.W_dn + b_dn

// f32x2 packed helpers ------------------------------------------------------
__device__ __forceinline__ unsigned long long pk2(float lo, float hi) {
    unsigned long long r;
    asm("mov.b64 %0, {%1, %2};" : "=l"(r) : "f"(lo), "f"(hi));
    return r;
}
__device__ __forceinline__ void upk2(unsigned long long v, float& lo, float& hi) {
    asm("mov.b64 {%0, %1}, %2;" : "=f"(lo), "=f"(hi) : "l"(v));
}
#define FMA2(d, a, b, c) \
    asm("fma.rn.f32x2 %0, %1, %2, %3;" : "=l"(d) : "l"(a), "l"(b), "l"(c))
#define ADD2(d, a, b) \
    asm("add.rn.f32x2 %0, %1, %2;" : "=l"(d) : "l"(a), "l"(b))

__device__ __forceinline__ float warp_sum(float v) {
#pragma unroll
    for (int o = 16; o; o >>= 1) v += __shfl_xor_sync(0xffffffffu, v, o);
    return v;
}

// ---------------------------------------------------------------------------
// Edge pass + embedded prep folds (unchanged from R3).
__global__ __launch_bounds__(256) void edge_kernel(
    const float* __restrict__ edges, const int* __restrict__ senders,
    const int* __restrict__ receivers, float* __restrict__ edges_out,
    const float* __restrict__ g, const float* __restrict__ W_en,
    const float* __restrict__ b_en, const float* __restrict__ W_ee,
    const float* __restrict__ b_ee, const float* __restrict__ W1,
    const float* __restrict__ b1, const float* __restrict__ W2,
    const float* __restrict__ b2, const float* __restrict__ W_dn,
    const float* __restrict__ b_dn, const float* __restrict__ W_de,
    const float* __restrict__ b_de) {
    __shared__ float s_edec[4];
    int tid = threadIdx.x;
    int lane = tid & 31;
    int warp = tid >> 5;

    if (warp < 4) {
        float acc = 0.f;
        const float* A = (warp < 3) ? (W_ee + warp * L) : b_ee;
#pragma unroll
        for (int q = 0; q < 4; q++) {
            int m = lane + 32 * q;
            acc += A[m] * W_de[m];
        }
        acc = warp_sum(acc);
        if (lane == 0) s_edec[warp] = (warp == 3) ? acc + b_de[0] : acc;
    }

    int gw = blockIdx.x * 8 + warp;
    if (gw < L * KEFF) {
        int k = gw >> 7;
        int j = gw & (L - 1);
        const float* A;
        int base;
        if (k < 16)      { A = W_en + k * L;        base = 0; }
        else if (k < 19) { A = W_ee + (k - 16) * L; base = L; }
        else if (k == 19){ A = b_ee;                base = L; }
        else if (k < 23) { A = W_ee + (k - 20) * L; base = 2 * L; }
        else             { A = b_ee;                base = 2 * L; }
        float acc = 0.f;
#pragma unroll
        for (int q = 0; q < 4; q++) {
            int m = lane + 32 * q;
            acc += A[m] * W1[(size_t)(base + m) * L + j];
        }
        acc = warp_sum(acc);
        if (lane == 0) g_W1eff[j * KEFF + k] = acc;
    } else if (gw < L * KEFF + L) {
        int j = gw - L * KEFF;
        float acc = 0.f;
#pragma unroll
        for (int q = 0; q < 4; q++) {
            int m = lane + 32 * q;
            acc += b_en[m] * W1[(size_t)m * L + j];
        }
        if (lane < 8) acc += g[lane] * W1[(size_t)(3 * L + lane) * L + j];
        acc = warp_sum(acc);
        if (lane == 0) g_b1eff[j] = acc + b1[j];
    } else if (gw < L * KEFF + 2 * L) {
        int k = gw - L * KEFF - L;
        float acc = 0.f;
#pragma unroll
        for (int q = 0; q < 4; q++) {
            int j = lane + 32 * q;
            acc += W2[(size_t)k * L + j] * W_dn[j];
        }
        acc = warp_sum(acc);
        if (lane == 0) g_w2d[k] = acc;
    } else if (gw == L * KEFF + 2 * L) {
        float acc = 0.f;
#pragma unroll
        for (int q = 0; q < 4; q++) {
            int j = lane + 32 * q;
            acc += b2[j] * W_dn[j];
        }
        acc = warp_sum(acc);
        if (lane == 0) g_cd[0] = acc + b_dn[0];
    }
    __syncthreads();

    int e = blockIdx.x * blockDim.x + tid;
    if (e >= NE) return;

    float w0 = s_edec[0], w1 = s_edec[1], w2 = s_edec[2], c = s_edec[3];

    float x0 = __ldg(edges + 3 * e + 0);
    float x1 = __ldg(edges + 3 * e + 1);
    float x2 = __ldg(edges + 3 * e + 2);
    int s = senders[e];
    int r = receivers[e];

    float* ps = g_agg + (size_t)8 * s;
    float* pr = g_agg + (size_t)8 * r + 4;
    asm volatile("red.global.add.v4.f32 [%0], {%1, %2, %3, %4};" ::"l"(ps),
                 "f"(x0), "f"(x1), "f"(x2), "f"(1.0f)
                 : "memory");
    asm volatile("red.global.add.v4.f32 [%0], {%1, %2, %3, %4};" ::"l"(pr),
                 "f"(x0), "f"(x1), "f"(x2), "f"(1.0f)
                 : "memory");

    edges_out[e] = fmaf(x0, w0, fmaf(x1, w1, fmaf(x2, w2, c)));
}

// ---------------------------------------------------------------------------
// Node pass: packed f32x2, unit = (node-pair, j-quarter). Lanes 4q..4q+3
// share a pair; each computes 32 of the 128 hidden units; shfl-combine.
__global__ __launch_bounds__(256) void node_kernel(
    const float* __restrict__ nodes, float* __restrict__ nodes_out) {
    __shared__ unsigned long long sWp[L * KEFF];  // {w,w} packed, 24 KB
    __shared__ unsigned long long sBp[L];
    __shared__ unsigned long long sDp[L];

    int tid = threadIdx.x;
    for (int i = tid; i < L * KEFF; i += blockDim.x) {
        float w = g_W1eff[i];
        sWp[i] = pk2(w, w);
    }
    if (tid < L) {
        float b = g_b1eff[tid];
        sBp[tid] = pk2(b, b);
        float d = g_w2d[tid];
        sDp[tid] = pk2(d, d);
    }
    __syncthreads();

    int u = blockIdx.x * blockDim.x + tid;
    if (u >= NUNIT) return;
    int p = u >> 2;        // pair index
    int jq = u & 3;        // j quarter
    int n0 = 2 * p;

    unsigned long long in2[KEFF];
    {
        const float4* a = reinterpret_cast<const float4*>(nodes + (size_t)n0 * 16);
        const float4* b = reinterpret_cast<const float4*>(nodes + (size_t)(n0 + 1) * 16);
#pragma unroll
        for (int q = 0; q < 4; q++) {
            float4 va = __ldg(a + q);
            float4 vb = __ldg(b + q);
            in2[4 * q + 0] = pk2(va.x, vb.x);
            in2[4 * q + 1] = pk2(va.y, vb.y);
            in2[4 * q + 2] = pk2(va.z, vb.z);
            in2[4 * q + 3] = pk2(va.w, vb.w);
        }
        const float4* pa = reinterpret_cast<const float4*>(g_agg + (size_t)8 * n0);
        const float4* pb = reinterpret_cast<const float4*>(g_agg + (size_t)8 * (n0 + 1));
        float4 a0 = pa[0], a1 = pa[1];
        float4 b0 = pb[0], b1 = pb[1];
        in2[16] = pk2(a0.x, b0.x); in2[17] = pk2(a0.y, b0.y);
        in2[18] = pk2(a0.z, b0.z); in2[19] = pk2(a0.w, b0.w);
        in2[20] = pk2(a1.x, b1.x); in2[21] = pk2(a1.y, b1.y);
        in2[22] = pk2(a1.z, b1.z); in2[23] = pk2(a1.w, b1.w);
    }

    unsigned long long out2 = 0;  // pk2(0,0)
    int j0 = jq * 32;

#pragma unroll 2
    for (int jj = 0; jj < 32; jj++) {
        int j = j0 + jj;
        // two independent accumulator chains, joined before relu
        unsigned long long acca = sBp[j];
        unsigned long long accb = 0;
        const ulonglong2* wr = reinterpret_cast<const ulonglong2*>(sWp + j * KEFF);
#pragma unroll
        for (int q = 0; q < 6; q++) {
            ulonglong2 wA = wr[2 * q];
            ulonglong2 wB = wr[2 * q + 1];
            FMA2(acca, in2[4 * q + 0], wA.x, acca);
            FMA2(accb, in2[4 * q + 1], wA.y, accb);
            FMA2(acca, in2[4 * q + 2], wB.x, acca);
            FMA2(accb, in2[4 * q + 3], wB.y, accb);
        }
        unsigned long long acc;
        ADD2(acc, acca, accb);
        float lo, hi;
        upk2(acc, lo, hi);
        unsigned long long r2 = pk2(fmaxf(lo, 0.f), fmaxf(hi, 0.f));
        FMA2(out2, r2, sDp[j], out2);
    }

    // combine the four j-quarters (lanes 4q..4q+3 of this warp)
    float o0, o1;
    upk2(out2, o0, o1);
    o0 += __shfl_xor_sync(0xffffffffu, o0, 1);
    o0 += __shfl_xor_sync(0xffffffffu, o0, 2);
    o1 += __shfl_xor_sync(0xffffffffu, o1, 1);
    o1 += __shfl_xor_sync(0xffffffffu, o1, 2);

    if (jq == 0) {
        float cd = g_cd[0];
        nodes_out[n0] = o0 + cd;
        nodes_out[n0 + 1] = o1 + cd;
    }
}

// ---------------------------------------------------------------------------
extern "C" void kernel_launch(void* const* d_in, const int* in_sizes, int n_in,
                              void* d_out, int out_size) {
    const float* nodes     = (const float*)d_in[0];
    const float* edges     = (const float*)d_in[1];
    const float* globals_  = (const float*)d_in[2];
    const int*   senders   = (const int*)d_in[3];
    const int*   receivers = (const int*)d_in[4];
    const float* W_en = (const float*)d_in[5];
    const float* b_en = (const float*)d_in[6];
    const float* W_ee = (const float*)d_in[7];
    const float* b_ee = (const float*)d_in[8];
    const float* W1   = (const float*)d_in[9];
    const float* b1   = (const float*)d_in[10];
    const float* W2   = (const float*)d_in[11];
    const float* b2   = (const float*)d_in[12];
    const float* W_dn = (const float*)d_in[13];
    const float* b_dn = (const float*)d_in[14];
    const float* W_de = (const float*)d_in[15];
    const float* b_de = (const float*)d_in[16];

    float* out = (float*)d_out;
    float* nodes_out = out;          // [50000]
    float* edges_out = out + NN;     // [800000]

    void* agg_ptr = nullptr;
    cudaGetSymbolAddress(&agg_ptr, g_agg);
    cudaMemsetAsync(agg_ptr, 0, (size_t)NN * 8 * sizeof(float), 0);

    edge_kernel<<<(NE + 255) / 256, 256>>>(
        edges, senders, receivers, edges_out, globals_, W_en, b_en, W_ee, b_ee,
        W1, b1, W2, b2, W_dn, b_dn, W_de, b_de);
    node_kernel<<<(NUNIT + 255) / 256, 256>>>(nodes, nodes_out);
}

// round 6
// speedup vs baseline: 3.1641x; 3.1641x over previous
#include <cuda_runtime.h>

#define NN 50000
#define NE 800000
#define L 128
#define KEFF 24   // 16 node feats + 3 agg_s + 1 cnt_s + 3 agg_r + 1 cnt_r
#define JP (L / 2)  // 64 packed hidden-unit pairs

// Scratch (__device__ globals; no allocation allowed)
__device__ float g_agg[NN * 8];       // per node: {s0,s1,s2,cnt_s, r0,r1,r2,cnt_r}
__device__ float g_W1eff[L * KEFF];   // [j*24+k] folded layer-1 weight
__device__ float g_b1eff[L];          // folded layer-1 bias
__device__ float g_w2d[L];            // W2 @ W_dn
__device__ float g_cd[1];             // b2.W_dn + b_dn

// f32x2 packed helpers ------------------------------------------------------
__device__ __forceinline__ unsigned long long pk2(float lo, float hi) {
    unsigned long long r;
    asm("mov.b64 %0, {%1, %2};" : "=l"(r) : "f"(lo), "f"(hi));
    return r;
}
__device__ __forceinline__ void upk2(unsigned long long v, float& lo, float& hi) {
    asm("mov.b64 {%0, %1}, %2;" : "=f"(lo), "=f"(hi) : "l"(v));
}
#define FMA2(d, a, b, c) \
    asm("fma.rn.f32x2 %0, %1, %2, %3;" : "=l"(d) : "l"(a), "l"(b), "l"(c))
#define ADD2(d, a, b) \
    asm("add.rn.f32x2 %0, %1, %2;" : "=l"(d) : "l"(a), "l"(b))

__device__ __forceinline__ float warp_sum(float v) {
#pragma unroll
    for (int o = 16; o; o >>= 1) v += __shfl_xor_sync(0xffffffffu, v, o);
    return v;
}

// ---------------------------------------------------------------------------
// Edge pass + embedded prep folds (unchanged — 13.9us incl. overheads in R3).
__global__ __launch_bounds__(256) void edge_kernel(
    const float* __restrict__ edges, const int* __restrict__ senders,
    const int* __restrict__ receivers, float* __restrict__ edges_out,
    const float* __restrict__ g, const float* __restrict__ W_en,
    const float* __restrict__ b_en, const float* __restrict__ W_ee,
    const float* __restrict__ b_ee, const float* __restrict__ W1,
    const float* __restrict__ b1, const float* __restrict__ W2,
    const float* __restrict__ b2, const float* __restrict__ W_dn,
    const float* __restrict__ b_dn, const float* __restrict__ W_de,
    const float* __restrict__ b_de) {
    __shared__ float s_edec[4];
    int tid = threadIdx.x;
    int lane = tid & 31;
    int warp = tid >> 5;

    if (warp < 4) {
        float acc = 0.f;
        const float* A = (warp < 3) ? (W_ee + warp * L) : b_ee;
#pragma unroll
        for (int q = 0; q < 4; q++) {
            int m = lane + 32 * q;
            acc += A[m] * W_de[m];
        }
        acc = warp_sum(acc);
        if (lane == 0) s_edec[warp] = (warp == 3) ? acc + b_de[0] : acc;
    }

    int gw = blockIdx.x * 8 + warp;
    if (gw < L * KEFF) {
        int k = gw >> 7;
        int j = gw & (L - 1);
        const float* A;
        int base;
        if (k < 16)      { A = W_en + k * L;        base = 0; }
        else if (k < 19) { A = W_ee + (k - 16) * L; base = L; }
        else if (k == 19){ A = b_ee;                base = L; }
        else if (k < 23) { A = W_ee + (k - 20) * L; base = 2 * L; }
        else             { A = b_ee;                base = 2 * L; }
        float acc = 0.f;
#pragma unroll
        for (int q = 0; q < 4; q++) {
            int m = lane + 32 * q;
            acc += A[m] * W1[(size_t)(base + m) * L + j];
        }
        acc = warp_sum(acc);
        if (lane == 0) g_W1eff[j * KEFF + k] = acc;
    } else if (gw < L * KEFF + L) {
        int j = gw - L * KEFF;
        float acc = 0.f;
#pragma unroll
        for (int q = 0; q < 4; q++) {
            int m = lane + 32 * q;
            acc += b_en[m] * W1[(size_t)m * L + j];
        }
        if (lane < 8) acc += g[lane] * W1[(size_t)(3 * L + lane) * L + j];
        acc = warp_sum(acc);
        if (lane == 0) g_b1eff[j] = acc + b1[j];
    } else if (gw < L * KEFF + 2 * L) {
        int k = gw - L * KEFF - L;
        float acc = 0.f;
#pragma unroll
        for (int q = 0; q < 4; q++) {
            int j = lane + 32 * q;
            acc += W2[(size_t)k * L + j] * W_dn[j];
        }
        acc = warp_sum(acc);
        if (lane == 0) g_w2d[k] = acc;
    } else if (gw == L * KEFF + 2 * L) {
        float acc = 0.f;
#pragma unroll
        for (int q = 0; q < 4; q++) {
            int j = lane + 32 * q;
            acc += b2[j] * W_dn[j];
        }
        acc = warp_sum(acc);
        if (lane == 0) g_cd[0] = acc + b_dn[0];
    }
    __syncthreads();

    int e = blockIdx.x * blockDim.x + tid;
    if (e >= NE) return;

    float w0 = s_edec[0], w1 = s_edec[1], w2 = s_edec[2], c = s_edec[3];

    float x0 = __ldg(edges + 3 * e + 0);
    float x1 = __ldg(edges + 3 * e + 1);
    float x2 = __ldg(edges + 3 * e + 2);
    int s = senders[e];
    int r = receivers[e];

    float* ps = g_agg + (size_t)8 * s;
    float* pr = g_agg + (size_t)8 * r + 4;
    asm volatile("red.global.add.v4.f32 [%0], {%1, %2, %3, %4};" ::"l"(ps),
                 "f"(x0), "f"(x1), "f"(x2), "f"(1.0f)
                 : "memory");
    asm volatile("red.global.add.v4.f32 [%0], {%1, %2, %3, %4};" ::"l"(pr),
                 "f"(x0), "f"(x1), "f"(x2), "f"(1.0f)
                 : "memory");

    edges_out[e] = fmaf(x0, w0, fmaf(x1, w1, fmaf(x2, w2, c)));
}

// ---------------------------------------------------------------------------
// Node pass: ONE node per thread; f32x2 packs hidden-unit pairs (2j, 2j+1).
// All lanes of a warp read the same sWp row -> pure smem broadcast.
// block=128 -> grid=391 CTAs (was 98) for SM coverage.
__global__ __launch_bounds__(128) void node_kernel(
    const float* __restrict__ nodes, float* __restrict__ nodes_out) {
    __shared__ unsigned long long sWp[JP * KEFF];  // {w[2j][k], w[2j+1][k]}, 12 KB
    __shared__ unsigned long long sBp[JP];         // {b[2j], b[2j+1]}
    __shared__ unsigned long long sDp[JP];         // {d[2j], d[2j+1]}

    int tid = threadIdx.x;
    for (int i = tid; i < JP * KEFF; i += blockDim.x) {
        int jp = i / KEFF;
        int k = i - jp * KEFF;
        sWp[i] = pk2(g_W1eff[(2 * jp) * KEFF + k], g_W1eff[(2 * jp + 1) * KEFF + k]);
    }
    if (tid < JP) {
        sBp[tid] = pk2(g_b1eff[2 * tid], g_b1eff[2 * tid + 1]);
        sDp[tid] = pk2(g_w2d[2 * tid], g_w2d[2 * tid + 1]);
    }
    __syncthreads();

    int n = blockIdx.x * blockDim.x + tid;
    if (n >= NN) return;

    // 24 inputs, each packed {x,x}
    unsigned long long in2[KEFF];
    {
        const float4* np = reinterpret_cast<const float4*>(nodes + (size_t)n * 16);
#pragma unroll
        for (int q = 0; q < 4; q++) {
            float4 v = __ldg(np + q);
            in2[4 * q + 0] = pk2(v.x, v.x);
            in2[4 * q + 1] = pk2(v.y, v.y);
            in2[4 * q + 2] = pk2(v.z, v.z);
            in2[4 * q + 3] = pk2(v.w, v.w);
        }
        const float4* pa = reinterpret_cast<const float4*>(g_agg + (size_t)8 * n);
        float4 a0 = pa[0], a1 = pa[1];
        in2[16] = pk2(a0.x, a0.x); in2[17] = pk2(a0.y, a0.y);
        in2[18] = pk2(a0.z, a0.z); in2[19] = pk2(a0.w, a0.w);
        in2[20] = pk2(a1.x, a1.x); in2[21] = pk2(a1.y, a1.y);
        in2[22] = pk2(a1.z, a1.z); in2[23] = pk2(a1.w, a1.w);
    }

    unsigned long long out2 = 0;

#pragma unroll 4
    for (int jp = 0; jp < JP; jp++) {
        unsigned long long acca = sBp[jp];
        unsigned long long accb = 0;
        const ulonglong2* wr = reinterpret_cast<const ulonglong2*>(sWp + jp * KEFF);
#pragma unroll
        for (int q = 0; q < 6; q++) {
            ulonglong2 w = wr[2 * q];
            ulonglong2 w2v = wr[2 * q + 1];
            FMA2(acca, in2[4 * q + 0], w.x, acca);
            FMA2(accb, in2[4 * q + 1], w.y, accb);
            FMA2(acca, in2[4 * q + 2], w2v.x, acca);
            FMA2(accb, in2[4 * q + 3], w2v.y, accb);
        }
        unsigned long long acc;
        ADD2(acc, acca, accb);
        float lo, hi;
        upk2(acc, lo, hi);
        unsigned long long r2 = pk2(fmaxf(lo, 0.f), fmaxf(hi, 0.f));
        FMA2(out2, r2, sDp[jp], out2);
    }

    float o0, o1;
    upk2(out2, o0, o1);
    nodes_out[n] = o0 + o1 + g_cd[0];
}

// ---------------------------------------------------------------------------
extern "C" void kernel_launch(void* const* d_in, const int* in_sizes, int n_in,
                              void* d_out, int out_size) {
    const float* nodes     = (const float*)d_in[0];
    const float* edges     = (const float*)d_in[1];
    const float* globals_  = (const float*)d_in[2];
    const int*   senders   = (const int*)d_in[3];
    const int*   receivers = (const int*)d_in[4];
    const float* W_en = (const float*)d_in[5];
    const float* b_en = (const float*)d_in[6];
    const float* W_ee = (const float*)d_in[7];
    const float* b_ee = (const float*)d_in[8];
    const float* W1   = (const float*)d_in[9];
    const float* b1   = (const float*)d_in[10];
    const float* W2   = (const float*)d_in[11];
    const float* b2   = (const float*)d_in[12];
    const float* W_dn = (const float*)d_in[13];
    const float* b_dn = (const float*)d_in[14];
    const float* W_de = (const float*)d_in[15];
    const float* b_de = (const float*)d_in[16];

    float* out = (float*)d_out;
    float* nodes_out = out;          // [50000]
    float* edges_out = out + NN;     // [800000]

    void* agg_ptr = nullptr;
    cudaGetSymbolAddress(&agg_ptr, g_agg);
    cudaMemsetAsync(agg_ptr, 0, (size_t)NN * 8 * sizeof(float), 0);

    edge_kernel<<<(NE + 255) / 256, 256>>>(
        edges, senders, receivers, edges_out, globals_, W_en, b_en, W_ee, b_ee,
        W1, b1, W2, b2, W_dn, b_dn, W_de, b_de);
    node_kernel<<<(NN + 127) / 128, 128>>>(nodes, nodes_out);
}